// round 2
// baseline (speedup 1.0000x reference)
#include <cuda_runtime.h>
#include <cuda_bf16.h>
#include <cstdint>

// Problem constants
#define NN   4096
#define DD   128
#define HH   8
#define ALPHA 0.2f
#define LN_EPS 1e-5f

typedef unsigned long long u64;

// ---------------- scratch (device globals; no allocation allowed) ----------------
__device__ float  g_wh[(size_t)HH * NN * DD];     // [h][n][d]  16 MB
__device__ float4 g_fq[HH * NN];                  // (f1, e^f1, e^{a f1}, 0)
__device__ float4 g_fk[HH * NN];                  // (f2, e^f2, e^{a f2}, 0)
__device__ float  g_cat[(size_t)NN * (HH * DD)];  // [n][h*128+d] 16 MB

// ---------------- f32x2 helpers ----------------
__device__ __forceinline__ u64 pack2(float x, float y) {
    u64 r; asm("mov.b64 %0, {%1, %2};" : "=l"(r) : "f"(x), "f"(y)); return r;
}
__device__ __forceinline__ float2 unpack2(u64 v) {
    float2 r; asm("mov.b64 {%0, %1}, %2;" : "=f"(r.x), "=f"(r.y) : "l"(v)); return r;
}
__device__ __forceinline__ u64 ffma2(u64 a, u64 b, u64 c) {
    u64 d; asm("fma.rn.f32x2 %0, %1, %2, %3;" : "=l"(d) : "l"(a), "l"(b), "l"(c)); return d;
}
__device__ __forceinline__ float elu1(float x) { return x > 0.f ? x : expm1f(x); }

// =================================================================
// Kernel 1: Wh[h,n,e] = sum_d nodes[n,d] * W[h,d,e]
// grid (64, 8), block 256.  64-node tile per CTA.
// =================================================================
__global__ void wh_kernel(const float* __restrict__ nodes, const float* __restrict__ W) {
    __shared__ float ns[64][DD];
    const int h  = blockIdx.y;
    const int nb = blockIdx.x * 64;
    const int tid = threadIdx.x;

    // stage nodes tile (8192 floats = 2048 float4)
#pragma unroll
    for (int i = 0; i < 8; i++) {
        int f  = tid + 256 * i;
        int r  = f >> 5, c4 = f & 31;
        *(float4*)&ns[r][c4 * 4] = *(const float4*)&nodes[(size_t)(nb + r) * DD + c4 * 4];
    }
    __syncthreads();

    const int dg = tid & 31;   // dims dg*4 .. dg*4+3
    const int ng = tid >> 5;   // nodes ng*8 .. ng*8+7
    const float* Wb = W + (size_t)h * DD * DD;

    u64 acc[8][2];
#pragma unroll
    for (int n = 0; n < 8; n++) { acc[n][0] = 0ULL; acc[n][1] = 0ULL; }

#pragma unroll 4
    for (int k = 0; k < DD; k++) {
        float4 w4 = __ldg((const float4*)&Wb[k * DD + dg * 4]);
        u64 wxy = pack2(w4.x, w4.y);
        u64 wzw = pack2(w4.z, w4.w);
#pragma unroll
        for (int n = 0; n < 8; n++) {
            float s = ns[ng * 8 + n][k];
            u64 ss = pack2(s, s);
            acc[n][0] = ffma2(ss, wxy, acc[n][0]);
            acc[n][1] = ffma2(ss, wzw, acc[n][1]);
        }
    }

#pragma unroll
    for (int n = 0; n < 8; n++) {
        float2 a = unpack2(acc[n][0]);
        float2 b = unpack2(acc[n][1]);
        float4 o = make_float4(a.x, a.y, b.x, b.y);
        *(float4*)&g_wh[((size_t)h * NN + nb + ng * 8 + n) * DD + dg * 4] = o;
    }
}

// =================================================================
// Kernel 1b: per (h,n): f1 = Wh.a1, f2 = Wh.a2, plus exp factors.
// grid 4096, block 256 (8 warps; one (h,n) per warp)
// =================================================================
__global__ void fvec_kernel(const float* __restrict__ a1, const float* __restrict__ a2) {
    const int g    = blockIdx.x * 8 + (threadIdx.x >> 5);   // 0 .. 32767
    const int lane = threadIdx.x & 31;
    const int h = g >> 12;
    const int n = g & (NN - 1);

    float4 wh = *(const float4*)&g_wh[((size_t)h * NN + n) * DD + lane * 4];
    float4 A1 = __ldg((const float4*)&a1[h * DD + lane * 4]);
    float4 A2 = __ldg((const float4*)&a2[h * DD + lane * 4]);
    float s1 = wh.x * A1.x + wh.y * A1.y + wh.z * A1.z + wh.w * A1.w;
    float s2 = wh.x * A2.x + wh.y * A2.y + wh.z * A2.z + wh.w * A2.w;
#pragma unroll
    for (int o = 16; o > 0; o >>= 1) {
        s1 += __shfl_xor_sync(0xffffffffu, s1, o);
        s2 += __shfl_xor_sync(0xffffffffu, s2, o);
    }
    if (lane == 0) {
        g_fq[g] = make_float4(s1, expf(s1), expf(ALPHA * s1), 0.f);
        g_fk[g] = make_float4(s2, expf(s2), expf(ALPHA * s2), 0.f);
    }
}

// =================================================================
// Kernel 2: masked-softmax attention, factorized exp, fused ELU.
// grid (64, 8): 64-query tile per CTA for head h. block 256.
//   stage role : thread (sq = tid>>2, sub = tid&3) computes w for
//                8 j's of the 32-j chunk, accumulates l partial.
//   fma  role  : warp w owns queries w*8..w*8+7, lane owns 4 dims.
// =================================================================
__global__ void attn_kernel(const int* __restrict__ adj) {
    __shared__ float whs[32][DD];      // 16 KB : Wh chunk
    __shared__ float ws[32][64];       //  8 KB : weights chunk [jj][q]
    __shared__ float lparts[64][4];    //  1 KB

    const int h     = blockIdx.y;
    const int qbase = blockIdx.x * 64;
    const int tid   = threadIdx.x;

    const int sq  = tid >> 2;
    const int sub = tid & 3;
    const float4 fqv = g_fq[h * NN + qbase + sq];
    const float f1 = fqv.x, E1 = fqv.y, F1 = fqv.z;
    float lpart = 0.f;

    const int w    = tid >> 5;
    const int lane = tid & 31;

    u64 acc[8][2];
#pragma unroll
    for (int q = 0; q < 8; q++) { acc[q][0] = 0ULL; acc[q][1] = 0ULL; }

    const float*  whb = g_wh + (size_t)h * NN * DD;
    const float4* fkb = g_fk + h * NN;
    const int*    adjrow = adj + (size_t)(qbase + sq) * NN;

    for (int j0 = 0; j0 < NN; j0 += 32) {
        // ---- stage Wh chunk (1024 float4) ----
#pragma unroll
        for (int i = 0; i < 4; i++) {
            int f = tid + 256 * i;
            int r = f >> 5, c4 = f & 31;
            *(float4*)&whs[r][c4 * 4] = *(const float4*)&whb[(size_t)(j0 + r) * DD + c4 * 4];
        }
        // ---- stage weights ----
#pragma unroll
        for (int i = 0; i < 8; i++) {
            int jj = sub + 4 * i;
            float4 fk = __ldg(&fkb[j0 + jj]);
            int    av = __ldg(&adjrow[j0 + jj]);
            float  t  = f1 + fk.x;
            float  p  = (t >= 0.f) ? (E1 * fk.y) : (F1 * fk.z);
            float  wv = (av > 0) ? p : 0.f;
            ws[jj][sq] = wv;
            lpart += wv;
        }
        __syncthreads();

        // ---- FMA phase ----
#pragma unroll 8
        for (int jj = 0; jj < 32; jj++) {
            float4 wh4 = *(float4*)&whs[jj][lane * 4];
            u64 wxy = pack2(wh4.x, wh4.y);
            u64 wzw = pack2(wh4.z, wh4.w);
            float4 wa = *(float4*)&ws[jj][w * 8];
            float4 wb = *(float4*)&ws[jj][w * 8 + 4];
            u64 q0 = pack2(wa.x, wa.x); acc[0][0] = ffma2(q0, wxy, acc[0][0]); acc[0][1] = ffma2(q0, wzw, acc[0][1]);
            u64 q1 = pack2(wa.y, wa.y); acc[1][0] = ffma2(q1, wxy, acc[1][0]); acc[1][1] = ffma2(q1, wzw, acc[1][1]);
            u64 q2 = pack2(wa.z, wa.z); acc[2][0] = ffma2(q2, wxy, acc[2][0]); acc[2][1] = ffma2(q2, wzw, acc[2][1]);
            u64 q3 = pack2(wa.w, wa.w); acc[3][0] = ffma2(q3, wxy, acc[3][0]); acc[3][1] = ffma2(q3, wzw, acc[3][1]);
            u64 q4 = pack2(wb.x, wb.x); acc[4][0] = ffma2(q4, wxy, acc[4][0]); acc[4][1] = ffma2(q4, wzw, acc[4][1]);
            u64 q5 = pack2(wb.y, wb.y); acc[5][0] = ffma2(q5, wxy, acc[5][0]); acc[5][1] = ffma2(q5, wzw, acc[5][1]);
            u64 q6 = pack2(wb.z, wb.z); acc[6][0] = ffma2(q6, wxy, acc[6][0]); acc[6][1] = ffma2(q6, wzw, acc[6][1]);
            u64 q7 = pack2(wb.w, wb.w); acc[7][0] = ffma2(q7, wxy, acc[7][0]); acc[7][1] = ffma2(q7, wzw, acc[7][1]);
        }
        __syncthreads();
    }

    lparts[sq][sub] = lpart;
    __syncthreads();

    // normalize + ELU + write concat layout [n][h*128+d]
#pragma unroll
    for (int q = 0; q < 8; q++) {
        int qq = w * 8 + q;
        float l   = lparts[qq][0] + lparts[qq][1] + lparts[qq][2] + lparts[qq][3];
        float inv = 1.f / l;
        float2 a = unpack2(acc[q][0]);
        float2 b = unpack2(acc[q][1]);
        float4 o;
        o.x = elu1(a.x * inv);
        o.y = elu1(a.y * inv);
        o.z = elu1(b.x * inv);
        o.w = elu1(b.y * inv);
        *(float4*)&g_cat[(size_t)(qbase + qq) * (HH * DD) + h * DD + lane * 4] = o;
    }
}

// =================================================================
// Kernel 3: x = elu(cat @ W1 + b1); out = LN(nodes + x)
// grid 256 (16 nodes per CTA), block 128 (one output dim per thread)
// =================================================================
__global__ void out_kernel(const float* __restrict__ nodes,
                           const float* __restrict__ W1,
                           const float* __restrict__ b1,
                           const float* __restrict__ gamma,
                           const float* __restrict__ beta,
                           float* __restrict__ out) {
    __shared__ float cs[16][256];     // 16 KB cat chunk
    __shared__ float rbuf[16][DD];    //  8 KB residual rows

    const int nb  = blockIdx.x * 16;
    const int tid = threadIdx.x;      // output dim

    float acc[16];
#pragma unroll
    for (int n = 0; n < 16; n++) acc[n] = 0.f;

    for (int kc = 0; kc < 4; kc++) {
        __syncthreads();
        // stage cat chunk: 16 rows x 256 k  (1024 float4)
#pragma unroll
        for (int i = 0; i < 8; i++) {
            int f = tid + 128 * i;
            int r = f >> 6, c4 = f & 63;
            *(float4*)&cs[r][c4 * 4] =
                *(const float4*)&g_cat[(size_t)(nb + r) * (HH * DD) + kc * 256 + c4 * 4];
        }
        __syncthreads();

        for (int kk = 0; kk < 256; kk += 4) {
            int k = kc * 256 + kk;
            float w0 = __ldg(&W1[(size_t)(k + 0) * DD + tid]);
            float w1v = __ldg(&W1[(size_t)(k + 1) * DD + tid]);
            float w2 = __ldg(&W1[(size_t)(k + 2) * DD + tid]);
            float w3 = __ldg(&W1[(size_t)(k + 3) * DD + tid]);
#pragma unroll
            for (int n = 0; n < 16; n++) {
                float4 c = *(float4*)&cs[n][kk];
                acc[n] += c.x * w0;
                acc[n] += c.y * w1v;
                acc[n] += c.z * w2;
                acc[n] += c.w * w3;
            }
        }
    }
    __syncthreads();

    float bb = __ldg(&b1[tid]);
#pragma unroll
    for (int n = 0; n < 16; n++) {
        float x = elu1(acc[n] + bb);
        rbuf[n][tid] = nodes[(size_t)(nb + n) * DD + tid] + x;
    }
    __syncthreads();

    const int w    = tid >> 5;
    const int lane = tid & 31;
    float4 G = __ldg((const float4*)&gamma[lane * 4]);
    float4 B = __ldg((const float4*)&beta[lane * 4]);
#pragma unroll
    for (int nn = 0; nn < 4; nn++) {
        int n = w * 4 + nn;
        float4 r = *(float4*)&rbuf[n][lane * 4];
        float s  = r.x + r.y + r.z + r.w;
        float ss = r.x * r.x + r.y * r.y + r.z * r.z + r.w * r.w;
#pragma unroll
        for (int o = 16; o > 0; o >>= 1) {
            s  += __shfl_xor_sync(0xffffffffu, s, o);
            ss += __shfl_xor_sync(0xffffffffu, ss, o);
        }
        float mu   = s * (1.f / DD);
        float var  = ss * (1.f / DD) - mu * mu;
        float rstd = rsqrtf(var + LN_EPS);
        float4 o4;
        o4.x = (r.x - mu) * rstd * G.x + B.x;
        o4.y = (r.y - mu) * rstd * G.y + B.y;
        o4.z = (r.z - mu) * rstd * G.z + B.z;
        o4.w = (r.w - mu) * rstd * G.w + B.w;
        *(float4*)&out[(size_t)(nb + n) * DD + lane * 4] = o4;
    }
}

// =================================================================
extern "C" void kernel_launch(void* const* d_in, const int* in_sizes, int n_in,
                              void* d_out, int out_size) {
    const float* nodes = (const float*)d_in[0];
    const int*   adj   = (const int*)  d_in[1];
    const float* W     = (const float*)d_in[2];
    const float* a1    = (const float*)d_in[3];
    const float* a2    = (const float*)d_in[4];
    const float* W1    = (const float*)d_in[5];
    const float* b1    = (const float*)d_in[6];
    const float* gamma = (const float*)d_in[7];
    const float* beta  = (const float*)d_in[8];
    float* out = (float*)d_out;

    wh_kernel  <<<dim3(NN / 64, HH), 256>>>(nodes, W);
    fvec_kernel<<<(HH * NN) / 8,     256>>>(a1, a2);
    attn_kernel<<<dim3(NN / 64, HH), 256>>>(adj);
    out_kernel <<<NN / 16,           128>>>(nodes, W1, b1, gamma, beta, out);
}

// round 5
// speedup vs baseline: 2.6520x; 2.6520x over previous
#include <cuda_runtime.h>
#include <cuda_bf16.h>
#include <cstdint>

// Problem constants
#define NN   4096
#define DD   128
#define HH   8
#define ALPHA 0.2f
#define LN_EPS 1e-5f

typedef unsigned long long u64;

// ---------------- scratch (device globals; no allocation allowed) ----------------
// WhT in mma A-fragment order: [h][jt(512)][dt(8)][lane(32)][slot(4)], tf32-rounded
__device__ float    g_whF[(size_t)HH * 512 * 8 * 32 * 4];   // 16 MB
__device__ float4   g_fq [HH * NN];                 // (f1, e^f1, e^{a f1}, 0)
__device__ float4   g_fk [HH * NN];                 // (f2, e^f2, e^{a f2}, 0)
__device__ float    g_cat[(size_t)NN * (HH * DD)];  // [n][h*128+d], 16 MB
__device__ unsigned g_adjbits[NN * (NN / 32)];      // bit-packed adj, 2 MB

// ---------------- helpers ----------------
__device__ __forceinline__ u64 pack2(float x, float y) {
    u64 r; asm("mov.b64 %0, {%1, %2};" : "=l"(r) : "f"(x), "f"(y)); return r;
}
__device__ __forceinline__ float2 unpack2(u64 v) {
    float2 r; asm("mov.b64 {%0, %1}, %2;" : "=f"(r.x), "=f"(r.y) : "l"(v)); return r;
}
__device__ __forceinline__ u64 ffma2(u64 a, u64 b, u64 c) {
    u64 d; asm("fma.rn.f32x2 %0, %1, %2, %3;" : "=l"(d) : "l"(a), "l"(b), "l"(c)); return d;
}
__device__ __forceinline__ float elu1(float x) { return x > 0.f ? x : expm1f(x); }
// cvt.rna.tf32.f32 requires a .b32 destination register
__device__ __forceinline__ float to_tf32(float x) {
    uint32_t r; asm("cvt.rna.tf32.f32 %0, %1;" : "=r"(r) : "f"(x));
    return __uint_as_float(r);
}

// m16n8k8 tf32 mma: D(f32) += A(tf32,row) * B(tf32,col)
__device__ __forceinline__ void mma_tf32(float c[4], float4 a, float2 b) {
    uint32_t a0 = __float_as_uint(a.x), a1 = __float_as_uint(a.y);
    uint32_t a2 = __float_as_uint(a.z), a3 = __float_as_uint(a.w);
    uint32_t b0 = __float_as_uint(b.x), b1 = __float_as_uint(b.y);
    asm volatile(
        "mma.sync.aligned.m16n8k8.row.col.f32.tf32.tf32.f32 "
        "{%0,%1,%2,%3}, {%4,%5,%6,%7}, {%8,%9}, {%0,%1,%2,%3};"
        : "+f"(c[0]), "+f"(c[1]), "+f"(c[2]), "+f"(c[3])
        : "r"(a0), "r"(a1), "r"(a2), "r"(a3), "r"(b0), "r"(b1));
}

// =================================================================
// Kernel 0: bit-pack adjacency. One warp per 32 columns.
// =================================================================
__global__ void pack_kernel(const int* __restrict__ adj) {
    int w    = blockIdx.x * 8 + (threadIdx.x >> 5);
    int lane = threadIdx.x & 31;
    int av = adj[(size_t)w * 32 + lane];
    unsigned m = __ballot_sync(0xffffffffu, av > 0);
    if (lane == 0) g_adjbits[w] = m;
}

// =================================================================
// Kernel 1: Wh = nodes @ W[h]; writes
//   - g_whF  : tf32 A-fragment layout for the attention MMA
//   - g_fq/g_fk : f1/f2 + exp factors (fvec folded in)
// grid (64, 8), block 256. 64-node tile per CTA.
// =================================================================
__global__ void wh_kernel(const float* __restrict__ nodes, const float* __restrict__ W,
                          const float* __restrict__ a1, const float* __restrict__ a2) {
    __shared__ float ns[64][DD];
    const int h  = blockIdx.y;
    const int nb = blockIdx.x * 64;
    const int tid = threadIdx.x;

#pragma unroll
    for (int i = 0; i < 8; i++) {
        int f  = tid + 256 * i;
        int r  = f >> 5, c4 = f & 31;
        *(float4*)&ns[r][c4 * 4] = *(const float4*)&nodes[(size_t)(nb + r) * DD + c4 * 4];
    }
    __syncthreads();

    const int dg = tid & 31;   // lane: dims dg*4 .. dg*4+3
    const int ng = tid >> 5;   // warp: nodes ng*8 .. ng*8+7
    const float* Wb = W + (size_t)h * DD * DD;

    u64 acc[8][2];
#pragma unroll
    for (int n = 0; n < 8; n++) { acc[n][0] = 0ULL; acc[n][1] = 0ULL; }

#pragma unroll 4
    for (int k = 0; k < DD; k++) {
        float4 w4 = __ldg((const float4*)&Wb[k * DD + dg * 4]);
        u64 wxy = pack2(w4.x, w4.y);
        u64 wzw = pack2(w4.z, w4.w);
#pragma unroll
        for (int n = 0; n < 8; n++) {
            float s = ns[ng * 8 + n][k];
            u64 ss = pack2(s, s);
            acc[n][0] = ffma2(ss, wxy, acc[n][0]);
            acc[n][1] = ffma2(ss, wzw, acc[n][1]);
        }
    }

    float4 wh4[8];
#pragma unroll
    for (int n = 0; n < 8; n++) {
        float2 a = unpack2(acc[n][0]);
        float2 b = unpack2(acc[n][1]);
        wh4[n] = make_float4(a.x, a.y, b.x, b.y);
    }

    // ---- f1/f2 (fvec folded in) ----
    float4 A1 = __ldg((const float4*)&a1[h * DD + dg * 4]);
    float4 A2 = __ldg((const float4*)&a2[h * DD + dg * 4]);
    float s1[8], s2[8];
#pragma unroll
    for (int n = 0; n < 8; n++) {
        s1[n] = wh4[n].x * A1.x + wh4[n].y * A1.y + wh4[n].z * A1.z + wh4[n].w * A1.w;
        s2[n] = wh4[n].x * A2.x + wh4[n].y * A2.y + wh4[n].z * A2.z + wh4[n].w * A2.w;
    }
#pragma unroll
    for (int o = 16; o > 0; o >>= 1) {
#pragma unroll
        for (int n = 0; n < 8; n++) {
            s1[n] += __shfl_xor_sync(0xffffffffu, s1[n], o);
            s2[n] += __shfl_xor_sync(0xffffffffu, s2[n], o);
        }
    }
    if (dg < 8) {
        float v1 = s1[0], v2 = s2[0];
#pragma unroll
        for (int n = 1; n < 8; n++)
            if (dg == n) { v1 = s1[n]; v2 = s2[n]; }
        int node = nb + ng * 8 + dg;
        g_fq[h * NN + node] = make_float4(v1, expf(v1), expf(ALPHA * v1), 0.f);
        g_fk[h * NN + node] = make_float4(v2, expf(v2), expf(ALPHA * v2), 0.f);
    }

    // ---- tf32 A-fragment layout write ----
#pragma unroll
    for (int n = 0; n < 8; n++) {
        int j  = nb + ng * 8 + n;
        int jt = j >> 3, jj = j & 7;
        float* base = g_whF + ((size_t)(h * 512 + jt)) * 1024;
        float vals[4] = {wh4[n].x, wh4[n].y, wh4[n].z, wh4[n].w};
#pragma unroll
        for (int q = 0; q < 4; q++) {
            int d  = dg * 4 + q;
            int dt = d >> 4, dd = d & 15;
            int lane2 = ((dd & 7) << 2) | (jj & 3);
            int slot  = (dd >> 3) | ((jj >> 2) << 1);
            base[dt * 128 + lane2 * 4 + slot] = to_tf32(vals[q]);
        }
    }
}

// =================================================================
// Kernel 2: attention via mma.sync tf32, double-buffered P fragments.
// grid (32, 8): 128-query tile per CTA for head h. block 256.
// Warp wid owns d-tile [wid*16, wid*16+16); output n dim = 128 q.
// =================================================================
__global__ void __launch_bounds__(256) attn_kernel() {
    __shared__ float2 pbuf[2][4][16][32];   // 32 KB : P fragments [buf][kt][nt][lane]
    __shared__ float4 fqs[128];             //  2 KB
    __shared__ float  lsum[128];

    const int h     = blockIdx.y;
    const int qbase = blockIdx.x * 128;
    const int tid   = threadIdx.x;
    const int wid   = tid >> 5;
    const int lane  = tid & 31;
    const int kt = wid >> 1;     // k-step this warp produces P for
    const int nh = wid & 1;      // which q-half this warp produces P for
    const int r4 = lane >> 2;
    const int c4 = lane & 3;

    if (tid < 128) {
        fqs[tid]  = g_fq[h * NN + qbase + tid];
        lsum[tid] = 0.f;
    }

    float c[16][4];
#pragma unroll
    for (int nt = 0; nt < 16; nt++)
#pragma unroll
        for (int i = 0; i < 4; i++) c[nt][i] = 0.f;
    float lpart[8];
#pragma unroll
    for (int i = 0; i < 8; i++) lpart[i] = 0.f;

    const float4* fkb = g_fk + h * NN;
    const unsigned* ab = g_adjbits + (size_t)qbase * (NN / 32);

    // -------- P fragment producer for one 32-j chunk --------
#define COMPUTE_P(J0, BUF) do {                                                  \
    int _j0 = (J0);                                                              \
    float4 fka = __ldg(&fkb[_j0 + kt * 8 + c4]);                                 \
    float4 fkc = __ldg(&fkb[_j0 + kt * 8 + c4 + 4]);                             \
    int _w = _j0 >> 5;                                                           \
    _Pragma("unroll")                                                            \
    for (int i = 0; i < 8; i++) {                                                \
        int nt = nh * 8 + i;                                                     \
        int q  = nt * 8 + r4;                                                    \
        unsigned mw = __ldg(&ab[(size_t)q * (NN / 32) + _w]);                    \
        float4 fq = fqs[q];                                                      \
        float ta = fq.x + fka.x;                                                 \
        float va = (ta >= 0.f) ? fq.y * fka.y : fq.z * fka.z;                    \
        va = ((mw >> (kt * 8 + c4)) & 1u) ? va : 0.f;                            \
        va = to_tf32(va);                                                        \
        float tb = fq.x + fkc.x;                                                 \
        float vb = (tb >= 0.f) ? fq.y * fkc.y : fq.z * fkc.z;                    \
        vb = ((mw >> (kt * 8 + c4 + 4)) & 1u) ? vb : 0.f;                        \
        vb = to_tf32(vb);                                                        \
        lpart[i] += va + vb;                                                     \
        pbuf[BUF][kt][nt][lane] = make_float2(va, vb);                           \
    }                                                                            \
} while (0)

    COMPUTE_P(0, 0);
    __syncthreads();

    for (int ch = 0; ch < 128; ch++) {
        const int cur = ch & 1;
        if (ch + 1 < 128) COMPUTE_P((ch + 1) * 32, cur ^ 1);

        const float* whfp = g_whF + (((size_t)(h * 512 + ch * 4) * 8 + wid) * 32 + lane) * 4;
#pragma unroll
        for (int ks = 0; ks < 4; ks++) {
            float4 af = __ldg((const float4*)(whfp + ks * 1024));
#pragma unroll
            for (int nt = 0; nt < 16; nt++) {
                float2 b = pbuf[cur][ks][nt][lane];
                mma_tf32(c[nt], af, b);
            }
        }
        __syncthreads();
    }
#undef COMPUTE_P

    // -------- softmax denominators --------
#pragma unroll
    for (int i = 0; i < 8; i++) {
        float v = lpart[i];
        v += __shfl_xor_sync(0xffffffffu, v, 1);
        v += __shfl_xor_sync(0xffffffffu, v, 2);
        if (c4 == 0) atomicAdd(&lsum[(nh * 8 + i) * 8 + r4], v);
    }
    __syncthreads();

    // -------- normalize + ELU + scatter to concat layout --------
#pragma unroll
    for (int nt = 0; nt < 16; nt++) {
        int q0 = nt * 8 + 2 * c4;
        float inv0 = 1.f / lsum[q0];
        float inv1 = 1.f / lsum[q0 + 1];
        int d0 = wid * 16 + r4;
        size_t row0 = (size_t)(qbase + q0) * (HH * DD) + h * DD;
        size_t row1 = row0 + (HH * DD);
        g_cat[row0 + d0]     = elu1(c[nt][0] * inv0);
        g_cat[row1 + d0]     = elu1(c[nt][1] * inv1);
        g_cat[row0 + d0 + 8] = elu1(c[nt][2] * inv0);
        g_cat[row1 + d0 + 8] = elu1(c[nt][3] * inv1);
    }
}

// =================================================================
// Kernel 3: x = elu(cat @ W1 + b1); out = LN(nodes + x)
// grid 512 (8 nodes/CTA), block 256 (split-k halves)
// =================================================================
__global__ void out_kernel(const float* __restrict__ nodes,
                           const float* __restrict__ W1,
                           const float* __restrict__ b1,
                           const float* __restrict__ gamma,
                           const float* __restrict__ beta,
                           float* __restrict__ out) {
    __shared__ float cs[8][1024];    // 32 KB
    __shared__ float part[8][DD];    //  4 KB
    __shared__ float rbuf[8][DD];    //  4 KB

    const int nb  = blockIdx.x * 8;
    const int tid = threadIdx.x;
    const int kh  = tid >> 7;        // which k-half
    const int col = tid & 127;

#pragma unroll
    for (int i = 0; i < 8; i++) {
        int f = tid + 256 * i;
        int r = f >> 8, c4 = f & 255;
        *(float4*)&cs[r][c4 * 4] = *(const float4*)&g_cat[(size_t)(nb + r) * 1024 + c4 * 4];
    }
    __syncthreads();

    float acc[8];
#pragma unroll
    for (int n = 0; n < 8; n++) acc[n] = 0.f;

    const int kbeg = kh * 512;
    for (int k = kbeg; k < kbeg + 512; k += 4) {
        float w0  = __ldg(&W1[(size_t)(k + 0) * DD + col]);
        float w1v = __ldg(&W1[(size_t)(k + 1) * DD + col]);
        float w2  = __ldg(&W1[(size_t)(k + 2) * DD + col]);
        float w3  = __ldg(&W1[(size_t)(k + 3) * DD + col]);
#pragma unroll
        for (int n = 0; n < 8; n++) {
            float4 c = *(float4*)&cs[n][k];
            acc[n] += c.x * w0;
            acc[n] += c.y * w1v;
            acc[n] += c.z * w2;
            acc[n] += c.w * w3;
        }
    }

    if (kh == 1) {
#pragma unroll
        for (int n = 0; n < 8; n++) part[n][col] = acc[n];
    }
    __syncthreads();
    if (kh == 0) {
        float bb = __ldg(&b1[col]);
#pragma unroll
        for (int n = 0; n < 8; n++) {
            float x = elu1(acc[n] + part[n][col] + bb);
            rbuf[n][col] = nodes[(size_t)(nb + n) * DD + col] + x;
        }
    }
    __syncthreads();

    const int w    = tid >> 5;
    const int lane = tid & 31;
    float4 G = __ldg((const float4*)&gamma[lane * 4]);
    float4 B = __ldg((const float4*)&beta[lane * 4]);
    {
        float4 r = *(float4*)&rbuf[w][lane * 4];
        float s  = r.x + r.y + r.z + r.w;
        float ss = r.x * r.x + r.y * r.y + r.z * r.z + r.w * r.w;
#pragma unroll
        for (int o = 16; o > 0; o >>= 1) {
            s  += __shfl_xor_sync(0xffffffffu, s, o);
            ss += __shfl_xor_sync(0xffffffffu, ss, o);
        }
        float mu   = s * (1.f / DD);
        float var  = ss * (1.f / DD) - mu * mu;
        float rstd = rsqrtf(var + LN_EPS);
        float4 o4;
        o4.x = (r.x - mu) * rstd * G.x + B.x;
        o4.y = (r.y - mu) * rstd * G.y + B.y;
        o4.z = (r.z - mu) * rstd * G.z + B.z;
        o4.w = (r.w - mu) * rstd * G.w + B.w;
        *(float4*)&out[(size_t)(nb + w) * DD + lane * 4] = o4;
    }
}

// =================================================================
extern "C" void kernel_launch(void* const* d_in, const int* in_sizes, int n_in,
                              void* d_out, int out_size) {
    const float* nodes = (const float*)d_in[0];
    const int*   adj   = (const int*)  d_in[1];
    const float* W     = (const float*)d_in[2];
    const float* a1    = (const float*)d_in[3];
    const float* a2    = (const float*)d_in[4];
    const float* W1    = (const float*)d_in[5];
    const float* b1    = (const float*)d_in[6];
    const float* gamma = (const float*)d_in[7];
    const float* beta  = (const float*)d_in[8];
    float* out = (float*)d_out;

    pack_kernel<<<NN * (NN / 32) / 8, 256>>>(adj);
    wh_kernel  <<<dim3(NN / 64, HH), 256>>>(nodes, W, a1, a2);
    attn_kernel<<<dim3(NN / 128, HH), 256>>>();
    out_kernel <<<NN / 8, 256>>>(nodes, W1, b1, gamma, beta, out);
}